// round 12
// baseline (speedup 1.0000x reference)
#include <cuda_runtime.h>
#include <math.h>

#define T_SEQ   512
#define IN_DIM  1024
#define H_DIM   2048
#define OUT_DIM 1024
#define GRID_P  148
#define NTHR    256
#define MAXR    14                          // ceil(2048/148)
#define SMEM_BYTES (2 * MAXR * H_DIM * 4)   // 229376 B dynamic: W_h2h1 + W_h2h2

// ---------------- device scratch (no allocation allowed) --------------------
__device__ float g_pre1[(size_t)T_SEQ * H_DIM];   // x@W_i2h1^T + b_i2h1 + b_h2h1
__device__ float g_h1[2][H_DIM];
__device__ float g_h2[2][H_DIM];
__device__ unsigned g_ctrs[64];                   // [0]=bar1 (h1), [32]=bar2 (h2)

__device__ __forceinline__ float dot4(float4 a, float4 b) {
    return a.x * b.x + a.y * b.y + a.z * b.z + a.w * b.w;
}

__device__ __forceinline__ void bar_arrive(unsigned* c) {
    asm volatile("red.release.gpu.add.u32 [%0], %1;" :: "l"(c), "r"(1u) : "memory");
}
__device__ __forceinline__ void bar_spin(unsigned* c, unsigned target) {
    unsigned v;
    do {
        asm volatile("ld.acquire.gpu.u32 %0, [%1];" : "=r"(v) : "l"(c) : "memory");
    } while (v < target);
}

// ---------------------------------------------------------------------------
// Kernel 1: pre1[t][j] = x[t] @ W_i2h1[j] + b_i2h1[j] + b_h2h1[j]
// ---------------------------------------------------------------------------
#define BT 64
#define BJ 128
#define BK 32

__global__ __launch_bounds__(128) void pre_gemm(
    const float* __restrict__ X, const float* __restrict__ W,
    const float* __restrict__ b1, const float* __restrict__ b2)
{
    // reset barrier counters for the persistent kernel (each replay)
    if (blockIdx.x == 0 && blockIdx.y == 0 && threadIdx.x < 2)
        g_ctrs[threadIdx.x * 32] = 0;

    __shared__ float Xs[BT][BK + 1];
    __shared__ float Ws[BJ][BK + 1];
    const int tid = threadIdx.x;
    const int bt = blockIdx.y * BT;
    const int bj = blockIdx.x * BJ;
    const int tx = tid & 15;
    const int ty = tid >> 4;

    float acc[8][8];
#pragma unroll
    for (int i = 0; i < 8; i++)
#pragma unroll
        for (int j = 0; j < 8; j++) acc[i][j] = 0.f;

    for (int k0 = 0; k0 < IN_DIM; k0 += BK) {
#pragma unroll
        for (int i = tid; i < BT * (BK / 4); i += 128) {
            int t = i / (BK / 4), kq = i % (BK / 4);
            float4 v = *(const float4*)(X + (size_t)(bt + t) * IN_DIM + k0 + kq * 4);
            Xs[t][kq * 4 + 0] = v.x; Xs[t][kq * 4 + 1] = v.y;
            Xs[t][kq * 4 + 2] = v.z; Xs[t][kq * 4 + 3] = v.w;
        }
#pragma unroll
        for (int i = tid; i < BJ * (BK / 4); i += 128) {
            int j = i / (BK / 4), kq = i % (BK / 4);
            float4 v = *(const float4*)(W + (size_t)(bj + j) * IN_DIM + k0 + kq * 4);
            Ws[j][kq * 4 + 0] = v.x; Ws[j][kq * 4 + 1] = v.y;
            Ws[j][kq * 4 + 2] = v.z; Ws[j][kq * 4 + 3] = v.w;
        }
        __syncthreads();
#pragma unroll 8
        for (int kk = 0; kk < BK; kk++) {
            float a[8], b[8];
#pragma unroll
            for (int i = 0; i < 8; i++) a[i] = Xs[ty * 8 + i][kk];
#pragma unroll
            for (int j = 0; j < 8; j++) b[j] = Ws[tx * 8 + j][kk];
#pragma unroll
            for (int i = 0; i < 8; i++)
#pragma unroll
                for (int j = 0; j < 8; j++) acc[i][j] += a[i] * b[j];
        }
        __syncthreads();
    }
#pragma unroll
    for (int i = 0; i < 8; i++) {
        int t = bt + ty * 8 + i;
#pragma unroll
        for (int j = 0; j < 8; j++) {
            int col = bj + tx * 8 + j;
            g_pre1[(size_t)t * H_DIM + col] = acc[i][j] + __ldg(b1 + col) + __ldg(b2 + col);
        }
    }
}

// ---------------------------------------------------------------------------
// Kernel 2: persistent RNN, SPLIT-PHASE pipeline, two barriers, round trips
// hidden under the opposite phase's compute:
//   step t: [bar1 passed] load h1(t) -> A: h1(t+1) -> arrive bar1
//           [spin bar2: all B(t-1) done -- a full phase of slack] load h2(t-1)
//           -> B: h2(t) -> arrive bar2
//           [spin bar1: all A(t) done -- RT covered by our B compute]
// Stage-2 runs on 4 FULL warps (tid<128) -- full-mask shfl is safe.
// ---------------------------------------------------------------------------
__global__ __launch_bounds__(NTHR, 1) void rnn_persistent(
    const float* __restrict__ W_h2h1,
    const float* __restrict__ W_i2h2,
    const float* __restrict__ b_i2h2,
    const float* __restrict__ W_h2h2,
    const float* __restrict__ b_h2h2)
{
    extern __shared__ float smem[];
    float* Wsh1 = smem;                    // [MAXR][2048]
    float* Wsh2 = smem + MAXR * H_DIM;     // [MAXR][2048]
    __shared__ __align__(16) float red[16][32];   // 2KB (rows 14,15 scratch-only)
    __shared__ float bsum[16];

    const int tid = threadIdx.x;
    const int bid = blockIdx.x;
    const int r0 = (bid * H_DIM) / GRID_P;
    const int r1 = ((bid + 1) * H_DIM) / GRID_P;
    const int nr = r1 - r0;                // 13 or 14
    const int lane = tid & 31;
    const int wid = tid >> 5;

    // h1(0) = tanh(pre1[0]) (h1(-1)=0); h2(-1) = 0 lives in g_h2[1]
    if (tid < nr) {
        g_h1[0][r0 + tid] = tanhf(__ldg(&g_pre1[r0 + tid]));
        g_h2[1][r0 + tid] = 0.f;
        bsum[tid] = __ldg(b_i2h2 + r0 + tid) + __ldg(b_h2h2 + r0 + tid);
    }

    // SMEM weight caches (own rows of W_h2h1, W_h2h2)
    {
        const float4* s1 = (const float4*)(W_h2h1 + (size_t)r0 * H_DIM);
        const float4* s2 = (const float4*)(W_h2h2 + (size_t)r0 * H_DIM);
        float4* d1 = (float4*)Wsh1;
        float4* d2 = (float4*)Wsh2;
        const int n4 = nr * (H_DIM / 4);
        for (int i = tid; i < n4; i += NTHR) { d1[i] = s1[i]; d2[i] = s2[i]; }
    }

    // Register-stationary W_i2h2 slices (cols 4*tid.. and 1024+4*tid..)
    float4 wr0[MAXR], wr1[MAXR];
#pragma unroll
    for (int rr = 0; rr < MAXR; rr++) {
        int r = (rr < nr) ? (r0 + rr) : r0;
        const float4* wp = (const float4*)(W_i2h2 + (size_t)r * H_DIM);
        wr0[rr] = wp[tid];
        wr1[rr] = wp[tid + 256];
    }

    const unsigned G = GRID_P;
    // init barrier: publish h1(0), h2(-1), caches
    __syncthreads();
    if (tid == 0) {
        bar_arrive(&g_ctrs[0]);
        bar_arrive(&g_ctrs[32]);
        bar_spin(&g_ctrs[0], G);
        bar_spin(&g_ctrs[32], G);
    }
    __syncthreads();

    const int frow = tid >> 3;             // stage-2 row (0..15 for tid<128)
    const int fs = tid & 7;                // stage-2 float4 index
    const int prow = (frow < nr) ? frow : (nr - 1);   // clamped prefetch row

    for (int t = 0; t < T_SEQ - 1; t++) {
        const int q = t & 1;

        // prefetch pre1[t+1] for the A stage-2 rows
        float pre = __ldg(&g_pre1[(size_t)(t + 1) * H_DIM + r0 + prow]);

        // ---- phase A: h1(t+1) = tanh(pre1[t+1] + W_h2h1 @ h1(t)) ----
        float4 n0 = __ldcg((const float4*)g_h1[q] + tid);
        float4 n1 = __ldcg((const float4*)g_h1[q] + tid + 256);
#pragma unroll
        for (int rr = 0; rr < MAXR; rr++) {
            const float* w = Wsh1 + rr * H_DIM;
            float4 w0 = *(const float4*)(w + 4 * tid);
            float4 w1 = *(const float4*)(w + 4 * tid + 1024);
            float acc = dot4(w0, n0) + dot4(w1, n1);
            acc += __shfl_xor_sync(0xffffffffu, acc, 16);
            acc += __shfl_xor_sync(0xffffffffu, acc, 8);
            acc += __shfl_xor_sync(0xffffffffu, acc, 4);
            if (lane < 4) red[rr][wid * 4 + lane] = acc;
        }
        __syncthreads();
        if (tid < 128) {                    // 4 FULL warps (shfl-safe)
            float4 v = *((const float4*)red[frow] + fs);
            float x = (v.x + v.y) + (v.z + v.w);
            x += __shfl_down_sync(0xffffffffu, x, 4, 8);
            x += __shfl_down_sync(0xffffffffu, x, 2, 8);
            x += __shfl_down_sync(0xffffffffu, x, 1, 8);
            if (fs == 0 && frow < nr)
                g_h1[1 - q][r0 + frow] = tanhf(pre + x);
        }
        __syncthreads();                   // h1 stores complete before arrive
        if (tid == 0) {
            bar_arrive(&g_ctrs[0]);                       // publish h1(t+1)
            bar_spin(&g_ctrs[32], (unsigned)(t + 1) * G); // all B(t-1) done (slack)
        }
        __syncthreads();

        // ---- phase B: h2(t) = tanh(W_i2h2@h1(t) + W_h2h2@h2(t-1) + b) ----
        float4 c0 = __ldcg((const float4*)g_h2[1 - q] + tid);
        float4 c1 = __ldcg((const float4*)g_h2[1 - q] + tid + 256);
#pragma unroll
        for (int rr = 0; rr < MAXR; rr++) {
            const float* w = Wsh2 + rr * H_DIM;
            float4 w0 = *(const float4*)(w + 4 * tid);
            float4 w1 = *(const float4*)(w + 4 * tid + 1024);
            float acc = dot4(wr0[rr], n0) + dot4(wr1[rr], n1)
                      + dot4(w0, c0) + dot4(w1, c1);
            acc += __shfl_xor_sync(0xffffffffu, acc, 16);
            acc += __shfl_xor_sync(0xffffffffu, acc, 8);
            acc += __shfl_xor_sync(0xffffffffu, acc, 4);
            if (lane < 4) red[rr][wid * 4 + lane] = acc;
        }
        __syncthreads();
        if (tid < 128) {                    // 4 FULL warps
            float4 v = *((const float4*)red[frow] + fs);
            float x = (v.x + v.y) + (v.z + v.w);
            x += __shfl_down_sync(0xffffffffu, x, 4, 8);
            x += __shfl_down_sync(0xffffffffu, x, 2, 8);
            x += __shfl_down_sync(0xffffffffu, x, 1, 8);
            if (fs == 0 && frow < nr)
                g_h2[q][r0 + frow] = tanhf(bsum[frow] + x);
        }
        __syncthreads();                   // h2 stores complete before arrive
        if (tid == 0) {
            bar_arrive(&g_ctrs[32]);                      // publish h2(t)
            bar_spin(&g_ctrs[0], (unsigned)(t + 2) * G);  // all A(t): RT hidden by B
        }
        __syncthreads();
    }

    // ---- epilogue t = 511: h2(511) only ----
    {
        float4 n0 = __ldcg((const float4*)g_h1[1] + tid);           // h1(511)
        float4 n1 = __ldcg((const float4*)g_h1[1] + tid + 256);
        if (tid == 0)
            bar_spin(&g_ctrs[32], (unsigned)T_SEQ * G);             // all B(510)
        __syncthreads();
        float4 c0 = __ldcg((const float4*)g_h2[0] + tid);           // h2(510)
        float4 c1 = __ldcg((const float4*)g_h2[0] + tid + 256);
#pragma unroll
        for (int rr = 0; rr < MAXR; rr++) {
            const float* w = Wsh2 + rr * H_DIM;
            float4 w0 = *(const float4*)(w + 4 * tid);
            float4 w1 = *(const float4*)(w + 4 * tid + 1024);
            float acc = dot4(wr0[rr], n0) + dot4(wr1[rr], n1)
                      + dot4(w0, c0) + dot4(w1, c1);
            acc += __shfl_xor_sync(0xffffffffu, acc, 16);
            acc += __shfl_xor_sync(0xffffffffu, acc, 8);
            acc += __shfl_xor_sync(0xffffffffu, acc, 4);
            if (lane < 4) red[rr][wid * 4 + lane] = acc;
        }
        __syncthreads();
        if (tid < 128) {                    // 4 FULL warps
            float4 v = *((const float4*)red[frow] + fs);
            float x = (v.x + v.y) + (v.z + v.w);
            x += __shfl_down_sync(0xffffffffu, x, 4, 8);
            x += __shfl_down_sync(0xffffffffu, x, 2, 8);
            x += __shfl_down_sync(0xffffffffu, x, 1, 8);
            if (fs == 0 && frow < nr)
                g_h2[1][r0 + frow] = tanhf(bsum[frow] + x);
        }
    }
    // final h2 (t=511) is in g_h2[1]; kernel boundary publishes it
}

// ---------------------------------------------------------------------------
// Kernel 3: out = h2_final @ W_h2o2^T + b_h2o2
// ---------------------------------------------------------------------------
__global__ __launch_bounds__(256) void out_gemv(
    const float* __restrict__ W, const float* __restrict__ b,
    float* __restrict__ out)
{
    const int lane = threadIdx.x & 31;
    const int warp = threadIdx.x >> 5;
    const int row = blockIdx.x * 8 + warp;
    const float4* wp = (const float4*)(W + (size_t)row * H_DIM);
    const float4* hp = (const float4*)g_h2[1];
    float acc = 0.f;
#pragma unroll
    for (int i = 0; i < 16; i++) {
        float4 w4 = __ldg(wp + i * 32 + lane);
        float4 h4 = __ldcg(hp + i * 32 + lane);
        acc += dot4(w4, h4);
    }
#pragma unroll
    for (int off = 16; off; off >>= 1)
        acc += __shfl_xor_sync(0xffffffffu, acc, off);
    if (lane == 0) out[row] = acc + __ldg(b + row);
}

// ---------------------------------------------------------------------------
extern "C" void kernel_launch(void* const* d_in, const int* in_sizes, int n_in,
                              void* d_out, int out_size)
{
    const float* word   = (const float*)d_in[0];
    const float* W_i2h1 = (const float*)d_in[1];
    const float* b_i2h1 = (const float*)d_in[2];
    const float* W_h2h1 = (const float*)d_in[3];
    const float* b_h2h1 = (const float*)d_in[4];
    // d_in[5], d_in[6]: W_h2o1 / b_h2o1 — dead code in reference
    const float* W_i2h2 = (const float*)d_in[7];
    const float* b_i2h2 = (const float*)d_in[8];
    const float* W_h2h2 = (const float*)d_in[9];
    const float* b_h2h2 = (const float*)d_in[10];
    const float* W_h2o2 = (const float*)d_in[11];
    const float* b_h2o2 = (const float*)d_in[12];
    float* out = (float*)d_out;

    cudaFuncSetAttribute(rnn_persistent,
                         cudaFuncAttributeMaxDynamicSharedMemorySize, SMEM_BYTES);

    dim3 pg(H_DIM / BJ, T_SEQ / BT);
    pre_gemm<<<pg, 128>>>(word, W_i2h1, b_i2h1, b_h2h1);
    rnn_persistent<<<GRID_P, NTHR, SMEM_BYTES>>>(W_h2h1, W_i2h2, b_i2h2,
                                                 W_h2h2, b_h2h2);
    out_gemv<<<OUT_DIM / 8, 256>>>(W_h2o2, b_h2o2, out);
}

// round 14
// speedup vs baseline: 1.3160x; 1.3160x over previous
#include <cuda_runtime.h>
#include <math.h>

#define T_SEQ   512
#define IN_DIM  1024
#define H_DIM   2048
#define OUT_DIM 1024
#define GRID_P  148
#define NTHR    256
#define MAXR    14                          // ceil(2048/148)
#define SMEM_BYTES (2 * MAXR * H_DIM * 4)   // 229376 B dynamic: W_h2h1 + W_h2h2

// ---------------- device scratch (no allocation allowed) --------------------
__device__ float g_pre1[(size_t)T_SEQ * H_DIM];   // x@W_i2h1^T + b_i2h1 + b_h2h1
__device__ float g_h1[2][H_DIM];
__device__ float g_h2[2][H_DIM];
__device__ unsigned g_bar_ctr;                    // monotonic arrival counter

__device__ __forceinline__ float dot4(float4 a, float4 b) {
    return a.x * b.x + a.y * b.y + a.z * b.z + a.w * b.w;
}

// Grid barrier, return-free arrive: red.release.gpu.add (REDG -- no
// return-path serialization) + acquire spin by thread 0 on the single
// counter line. Monotonic: barrier k waits for ctr >= k*GRID_P.
// Reset by pre_gemm each replay.
__device__ __forceinline__ void grid_bar(unsigned target) {
    __syncthreads();
    if (threadIdx.x == 0) {
        asm volatile("red.release.gpu.add.u32 [%0], %1;"
                     :: "l"(&g_bar_ctr), "r"(1u) : "memory");
        unsigned v;
        do {
            asm volatile("ld.acquire.gpu.u32 %0, [%1];"
                         : "=r"(v) : "l"(&g_bar_ctr) : "memory");
        } while (v < target);
    }
    __syncthreads();
}

// ---------------------------------------------------------------------------
// Kernel 1: pre1[t][j] = x[t] @ W_i2h1[j] + b_i2h1[j] + b_h2h1[j]
// 256 CTAs (16 x 16) of 128 threads; 32x128 tile, 4x8 microtile.
// ---------------------------------------------------------------------------
#define BT 32
#define BJ 128
#define BK 32

__global__ __launch_bounds__(128) void pre_gemm(
    const float* __restrict__ X, const float* __restrict__ W,
    const float* __restrict__ b1, const float* __restrict__ b2)
{
    // reset barrier counter for the persistent kernel (each replay)
    if (blockIdx.x == 0 && blockIdx.y == 0 && threadIdx.x == 0)
        g_bar_ctr = 0;

    __shared__ float Xs[BT][BK + 1];
    __shared__ float Ws[BJ][BK + 1];
    const int tid = threadIdx.x;
    const int bt = blockIdx.y * BT;
    const int bj = blockIdx.x * BJ;
    const int tx = tid & 15;               // j group (8 cols each)
    const int ty = tid >> 4;               // t group (4 rows each)

    float acc[4][8];
#pragma unroll
    for (int i = 0; i < 4; i++)
#pragma unroll
        for (int j = 0; j < 8; j++) acc[i][j] = 0.f;

    for (int k0 = 0; k0 < IN_DIM; k0 += BK) {
#pragma unroll
        for (int i = tid; i < BT * (BK / 4); i += 128) {
            int t = i / (BK / 4), kq = i % (BK / 4);
            float4 v = *(const float4*)(X + (size_t)(bt + t) * IN_DIM + k0 + kq * 4);
            Xs[t][kq * 4 + 0] = v.x; Xs[t][kq * 4 + 1] = v.y;
            Xs[t][kq * 4 + 2] = v.z; Xs[t][kq * 4 + 3] = v.w;
        }
#pragma unroll
        for (int i = tid; i < BJ * (BK / 4); i += 128) {
            int j = i / (BK / 4), kq = i % (BK / 4);
            float4 v = *(const float4*)(W + (size_t)(bj + j) * IN_DIM + k0 + kq * 4);
            Ws[j][kq * 4 + 0] = v.x; Ws[j][kq * 4 + 1] = v.y;
            Ws[j][kq * 4 + 2] = v.z; Ws[j][kq * 4 + 3] = v.w;
        }
        __syncthreads();
#pragma unroll 8
        for (int kk = 0; kk < BK; kk++) {
            float a[4], b[8];
#pragma unroll
            for (int i = 0; i < 4; i++) a[i] = Xs[ty * 4 + i][kk];
#pragma unroll
            for (int j = 0; j < 8; j++) b[j] = Ws[tx * 8 + j][kk];
#pragma unroll
            for (int i = 0; i < 4; i++)
#pragma unroll
                for (int j = 0; j < 8; j++) acc[i][j] += a[i] * b[j];
        }
        __syncthreads();
    }
#pragma unroll
    for (int i = 0; i < 4; i++) {
        int t = bt + ty * 4 + i;
#pragma unroll
        for (int j = 0; j < 8; j++) {
            int col = bj + tx * 8 + j;
            g_pre1[(size_t)t * H_DIM + col] = acc[i][j] + __ldg(b1 + col) + __ldg(b2 + col);
        }
    }
}

// ---------------------------------------------------------------------------
// Kernel 2: persistent RNN (R7 structure). FUSED phases, ONE grid barrier per
// step. Stage-1: 4 xor-shuffles -> 2 partials/warp -> red[28][16].
// Stage-2: 4 threads/row (tid<128 = 4 FULL warps), float4 + 2 width-4 shfl.
// ---------------------------------------------------------------------------
__global__ __launch_bounds__(NTHR, 1) void rnn_persistent(
    const float* __restrict__ W_h2h1,
    const float* __restrict__ W_i2h2,
    const float* __restrict__ b_i2h2,
    const float* __restrict__ W_h2h2,
    const float* __restrict__ b_h2h2)
{
    extern __shared__ float smem[];
    float* Wsh1 = smem;                    // [MAXR][2048]
    float* Wsh2 = smem + MAXR * H_DIM;     // [MAXR][2048]
    __shared__ __align__(16) float red[32][16];   // 2KB (rows 28..31 scratch)
    __shared__ float bsum[16];

    const int tid = threadIdx.x;
    const int bid = blockIdx.x;
    const int r0 = (bid * H_DIM) / GRID_P;
    const int r1 = ((bid + 1) * H_DIM) / GRID_P;
    const int nr = r1 - r0;                // 13 or 14
    const int lane = tid & 31;
    const int wid = tid >> 5;

    // h1(0) = tanh(pre1[0]) (h1(-1)=0); h2(-1) = 0 lives in g_h2[1]
    if (tid < nr) {
        g_h1[0][r0 + tid] = tanhf(__ldg(&g_pre1[r0 + tid]));
        g_h2[1][r0 + tid] = 0.f;
        bsum[tid] = __ldg(b_i2h2 + r0 + tid) + __ldg(b_h2h2 + r0 + tid);
    }

    // SMEM weight caches (own rows of W_h2h1, W_h2h2)
    {
        const float4* s1 = (const float4*)(W_h2h1 + (size_t)r0 * H_DIM);
        const float4* s2 = (const float4*)(W_h2h2 + (size_t)r0 * H_DIM);
        float4* d1 = (float4*)Wsh1;
        float4* d2 = (float4*)Wsh2;
        const int n4 = nr * (H_DIM / 4);
        for (int i = tid; i < n4; i += NTHR) { d1[i] = s1[i]; d2[i] = s2[i]; }
    }

    // Register-stationary W_i2h2 slices (cols 4*tid.. and 1024+4*tid..)
    float4 wr0[MAXR], wr1[MAXR];
#pragma unroll
    for (int rr = 0; rr < MAXR; rr++) {
        int r = (rr < nr) ? (r0 + rr) : r0;
        const float4* wp = (const float4*)(W_i2h2 + (size_t)r * H_DIM);
        wr0[rr] = wp[tid];
        wr1[rr] = wp[tid + 256];
    }

    unsigned tgt = GRID_P;
    grid_bar(tgt);                         // h1(0), h2(-1), caches visible

    const int frow = tid >> 2;             // stage-2 row (0..31 for tid<128)
    const int fs = tid & 3;                // stage-2 float4 index (0..3)
    // clamped prefetch row for the A-part (rows 14..27 -> pre1 row)
    const int prowA = (frow >= MAXR && frow < 2 * MAXR)
                      ? (((frow - MAXR) < nr) ? (frow - MAXR) : (nr - 1)) : 0;

    for (int t = 0; t < T_SEQ - 1; t++) {
        const int q = t & 1;

        // prefetch pre1[t+1] for the A stage-2 rows
        float pre = __ldg(&g_pre1[(size_t)(t + 1) * H_DIM + r0 + prowA]);

        // single post-barrier load: h1(t) and h2(t-1) slices
        float4 n0 = __ldcg((const float4*)g_h1[q] + tid);
        float4 n1 = __ldcg((const float4*)g_h1[q] + tid + 256);
        float4 c0 = __ldcg((const float4*)g_h2[1 - q] + tid);
        float4 c1 = __ldcg((const float4*)g_h2[1 - q] + tid + 256);

        // ---- fused stage-1: accB -> h2(t) rows, accA -> h1(t+1) rows ----
#pragma unroll
        for (int rr = 0; rr < MAXR; rr++) {
            const float* w1 = Wsh1 + rr * H_DIM;
            const float* w2 = Wsh2 + rr * H_DIM;
            float4 w10 = *(const float4*)(w1 + 4 * tid);
            float4 w11 = *(const float4*)(w1 + 4 * tid + 1024);
            float4 w20 = *(const float4*)(w2 + 4 * tid);
            float4 w21 = *(const float4*)(w2 + 4 * tid + 1024);
            float accA = dot4(w10, n0) + dot4(w11, n1);
            float accB = dot4(wr0[rr], n0) + dot4(wr1[rr], n1)
                       + dot4(w20, c0) + dot4(w21, c1);
            accA += __shfl_xor_sync(0xffffffffu, accA, 16);
            accB += __shfl_xor_sync(0xffffffffu, accB, 16);
            accA += __shfl_xor_sync(0xffffffffu, accA, 8);
            accB += __shfl_xor_sync(0xffffffffu, accB, 8);
            accA += __shfl_xor_sync(0xffffffffu, accA, 4);
            accB += __shfl_xor_sync(0xffffffffu, accB, 4);
            accA += __shfl_xor_sync(0xffffffffu, accA, 2);
            accB += __shfl_xor_sync(0xffffffffu, accB, 2);
            if (lane < 2) {
                red[rr][wid * 2 + lane] = accB;          // even/odd partials
                red[MAXR + rr][wid * 2 + lane] = accA;
            }
        }
        __syncthreads();

        // ---- stage-2: 28 rows x 4 threads (4 FULL warps) ----
        if (tid < 128) {
            float4 v = *((const float4*)red[frow] + fs);
            float x = (v.x + v.y) + (v.z + v.w);
            x += __shfl_down_sync(0xffffffffu, x, 2, 4);
            x += __shfl_down_sync(0xffffffffu, x, 1, 4);
            if (fs == 0) {
                if (frow < MAXR) {                       // B: h2(t)
                    if (frow < nr)
                        g_h2[q][r0 + frow] = tanhf(bsum[frow] + x);
                } else if (frow < 2 * MAXR) {            // A: h1(t+1)
                    int ar = frow - MAXR;
                    if (ar < nr)
                        g_h1[1 - q][r0 + ar] = tanhf(pre + x);
                }
            }
        }
        tgt += GRID_P;
        grid_bar(tgt);     // the ONLY grid barrier of the step
    }

    // ---- epilogue t = 511: h2(511) only ----
    {
        float4 n0 = __ldcg((const float4*)g_h1[1] + tid);
        float4 n1 = __ldcg((const float4*)g_h1[1] + tid + 256);
        float4 c0 = __ldcg((const float4*)g_h2[0] + tid);
        float4 c1 = __ldcg((const float4*)g_h2[0] + tid + 256);
#pragma unroll
        for (int rr = 0; rr < MAXR; rr++) {
            const float* w2 = Wsh2 + rr * H_DIM;
            float4 w20 = *(const float4*)(w2 + 4 * tid);
            float4 w21 = *(const float4*)(w2 + 4 * tid + 1024);
            float accB = dot4(wr0[rr], n0) + dot4(wr1[rr], n1)
                       + dot4(w20, c0) + dot4(w21, c1);
            accB += __shfl_xor_sync(0xffffffffu, accB, 16);
            accB += __shfl_xor_sync(0xffffffffu, accB, 8);
            accB += __shfl_xor_sync(0xffffffffu, accB, 4);
            accB += __shfl_xor_sync(0xffffffffu, accB, 2);
            if (lane < 2) red[rr][wid * 2 + lane] = accB;
        }
        __syncthreads();
        if (tid < 128) {                    // 4 FULL warps
            float4 v = *((const float4*)red[frow] + fs);
            float x = (v.x + v.y) + (v.z + v.w);
            x += __shfl_down_sync(0xffffffffu, x, 2, 4);
            x += __shfl_down_sync(0xffffffffu, x, 1, 4);
            if (fs == 0 && frow < nr)
                g_h2[1][r0 + frow] = tanhf(bsum[frow] + x);
        }
    }
    // final h2 (t=511) is in g_h2[1]; kernel boundary publishes it
}

// ---------------------------------------------------------------------------
// Kernel 3: out = h2_final @ W_h2o2^T + b_h2o2
// ---------------------------------------------------------------------------
__global__ __launch_bounds__(256) void out_gemv(
    const float* __restrict__ W, const float* __restrict__ b,
    float* __restrict__ out)
{
    const int lane = threadIdx.x & 31;
    const int warp = threadIdx.x >> 5;
    const int row = blockIdx.x * 8 + warp;
    const float4* wp = (const float4*)(W + (size_t)row * H_DIM);
    const float4* hp = (const float4*)g_h2[1];
    float acc = 0.f;
#pragma unroll
    for (int i = 0; i < 16; i++) {
        float4 w4 = __ldg(wp + i * 32 + lane);
        float4 h4 = __ldcg(hp + i * 32 + lane);
        acc += dot4(w4, h4);
    }
#pragma unroll
    for (int off = 16; off; off >>= 1)
        acc += __shfl_xor_sync(0xffffffffu, acc, off);
    if (lane == 0) out[row] = acc + __ldg(b + row);
}

// ---------------------------------------------------------------------------
extern "C" void kernel_launch(void* const* d_in, const int* in_sizes, int n_in,
                              void* d_out, int out_size)
{
    const float* word   = (const float*)d_in[0];
    const float* W_i2h1 = (const float*)d_in[1];
    const float* b_i2h1 = (const float*)d_in[2];
    const float* W_h2h1 = (const float*)d_in[3];
    const float* b_h2h1 = (const float*)d_in[4];
    // d_in[5], d_in[6]: W_h2o1 / b_h2o1 — dead code in reference
    const float* W_i2h2 = (const float*)d_in[7];
    const float* b_i2h2 = (const float*)d_in[8];
    const float* W_h2h2 = (const float*)d_in[9];
    const float* b_h2h2 = (const float*)d_in[10];
    const float* W_h2o2 = (const float*)d_in[11];
    const float* b_h2o2 = (const float*)d_in[12];
    float* out = (float*)d_out;

    cudaFuncSetAttribute(rnn_persistent,
                         cudaFuncAttributeMaxDynamicSharedMemorySize, SMEM_BYTES);

    dim3 pg(H_DIM / BJ, T_SEQ / BT);                 // 16 x 16 = 256 blocks
    pre_gemm<<<pg, 128>>>(word, W_i2h1, b_i2h1, b_h2h1);
    rnn_persistent<<<GRID_P, NTHR, SMEM_BYTES>>>(W_h2h1, W_i2h2, b_i2h2,
                                                 W_h2h2, b_h2h2);
    out_gemv<<<OUT_DIM / 8, 256>>>(W_h2o2, b_h2o2, out);
}

// round 15
// speedup vs baseline: 1.4113x; 1.0724x over previous
#include <cuda_runtime.h>
#include <math.h>

#define T_SEQ   512
#define IN_DIM  1024
#define H_DIM   2048
#define OUT_DIM 1024
#define GRID_P  148
#define NTHR    256
#define MAXR    14                          // ceil(2048/148)
#define W1ROWS  13                          // Wsh1 rows in SMEM (row 13 -> regs)
#define SMEM_BYTES ((W1ROWS + MAXR) * H_DIM * 4)   // 221184 B dynamic

// ---------------- device scratch (no allocation allowed) --------------------
__device__ float g_pre1[(size_t)T_SEQ * H_DIM];   // x@W_i2h1^T + b_i2h1 + b_h2h1
__device__ float g_h1[2][H_DIM];
__device__ float g_h2[2][H_DIM];
__device__ unsigned g_bar_ctr;                    // monotonic arrival counter

__device__ __forceinline__ float dot4(float4 a, float4 b) {
    return a.x * b.x + a.y * b.y + a.z * b.z + a.w * b.w;
}

// Grid barrier, return-free arrive: red.release.gpu.add (REDG -- no
// return-path serialization) + acquire spin by thread 0 on the single
// counter line. Monotonic: barrier k waits for ctr >= k*GRID_P.
// Reset by pre_gemm each replay.
__device__ __forceinline__ void grid_bar(unsigned target) {
    __syncthreads();
    if (threadIdx.x == 0) {
        asm volatile("red.release.gpu.add.u32 [%0], %1;"
                     :: "l"(&g_bar_ctr), "r"(1u) : "memory");
        unsigned v;
        do {
            asm volatile("ld.acquire.gpu.u32 %0, [%1];"
                         : "=r"(v) : "l"(&g_bar_ctr) : "memory");
        } while (v < target);
    }
    __syncthreads();
}

// ---------------------------------------------------------------------------
// Kernel 1: pre1[t][j] = x[t] @ W_i2h1[j] + b_i2h1[j] + b_h2h1[j]
// (R7 version: 128 CTAs of 128 threads, 64x128 tile, 8x8 microtile, 94.7us)
// ---------------------------------------------------------------------------
#define BT 64
#define BJ 128
#define BK 32

__global__ __launch_bounds__(128) void pre_gemm(
    const float* __restrict__ X, const float* __restrict__ W,
    const float* __restrict__ b1, const float* __restrict__ b2)
{
    // reset barrier counter for the persistent kernel (each replay)
    if (blockIdx.x == 0 && blockIdx.y == 0 && threadIdx.x == 0)
        g_bar_ctr = 0;

    __shared__ float Xs[BT][BK + 1];
    __shared__ float Ws[BJ][BK + 1];
    const int tid = threadIdx.x;
    const int bt = blockIdx.y * BT;
    const int bj = blockIdx.x * BJ;
    const int tx = tid & 15;
    const int ty = tid >> 4;

    float acc[8][8];
#pragma unroll
    for (int i = 0; i < 8; i++)
#pragma unroll
        for (int j = 0; j < 8; j++) acc[i][j] = 0.f;

    for (int k0 = 0; k0 < IN_DIM; k0 += BK) {
#pragma unroll
        for (int i = tid; i < BT * (BK / 4); i += 128) {
            int t = i / (BK / 4), kq = i % (BK / 4);
            float4 v = *(const float4*)(X + (size_t)(bt + t) * IN_DIM + k0 + kq * 4);
            Xs[t][kq * 4 + 0] = v.x; Xs[t][kq * 4 + 1] = v.y;
            Xs[t][kq * 4 + 2] = v.z; Xs[t][kq * 4 + 3] = v.w;
        }
#pragma unroll
        for (int i = tid; i < BJ * (BK / 4); i += 128) {
            int j = i / (BK / 4), kq = i % (BK / 4);
            float4 v = *(const float4*)(W + (size_t)(bj + j) * IN_DIM + k0 + kq * 4);
            Ws[j][kq * 4 + 0] = v.x; Ws[j][kq * 4 + 1] = v.y;
            Ws[j][kq * 4 + 2] = v.z; Ws[j][kq * 4 + 3] = v.w;
        }
        __syncthreads();
#pragma unroll 8
        for (int kk = 0; kk < BK; kk++) {
            float a[8], b[8];
#pragma unroll
            for (int i = 0; i < 8; i++) a[i] = Xs[ty * 8 + i][kk];
#pragma unroll
            for (int j = 0; j < 8; j++) b[j] = Ws[tx * 8 + j][kk];
#pragma unroll
            for (int i = 0; i < 8; i++)
#pragma unroll
                for (int j = 0; j < 8; j++) acc[i][j] += a[i] * b[j];
        }
        __syncthreads();
    }
#pragma unroll
    for (int i = 0; i < 8; i++) {
        int t = bt + ty * 8 + i;
#pragma unroll
        for (int j = 0; j < 8; j++) {
            int col = bj + tx * 8 + j;
            g_pre1[(size_t)t * H_DIM + col] = acc[i][j] + __ldg(b1 + col) + __ldg(b2 + col);
        }
    }
}

// ---------------------------------------------------------------------------
// Kernel 2: persistent RNN. FUSED phases, ONE grid barrier per step.
// Wsh1 holds rows 0..12 in SMEM; row 13 of W_h2h1 lives in registers
// (wrA0/wrA1), freeing static smem for red[28][32] so stage-1 stops at
// THREE xor-shuffles (4 partials/warp, chain depth 3).
// Stage-2: 28 rows x 8 threads = tid<224 = 7 FULL warps (shfl-safe).
// ---------------------------------------------------------------------------
__global__ __launch_bounds__(NTHR, 1) void rnn_persistent(
    const float* __restrict__ W_h2h1,
    const float* __restrict__ W_i2h2,
    const float* __restrict__ b_i2h2,
    const float* __restrict__ W_h2h2,
    const float* __restrict__ b_h2h2)
{
    extern __shared__ float smem[];
    float* Wsh1 = smem;                         // [W1ROWS][2048]
    float* Wsh2 = smem + W1ROWS * H_DIM;        // [MAXR][2048]
    __shared__ __align__(16) float red[2 * MAXR][32];   // 3584B
    __shared__ float bsum[16];

    const int tid = threadIdx.x;
    const int bid = blockIdx.x;
    const int r0 = (bid * H_DIM) / GRID_P;
    const int r1 = ((bid + 1) * H_DIM) / GRID_P;
    const int nr = r1 - r0;                // 13 or 14
    const int lane = tid & 31;
    const int wid = tid >> 5;

    // h1(0) = tanh(pre1[0]) (h1(-1)=0); h2(-1) = 0 lives in g_h2[1]
    if (tid < nr) {
        g_h1[0][r0 + tid] = tanhf(__ldg(&g_pre1[r0 + tid]));
        g_h2[1][r0 + tid] = 0.f;
        bsum[tid] = __ldg(b_i2h2 + r0 + tid) + __ldg(b_h2h2 + r0 + tid);
    }

    // SMEM weight caches: W_h2h1 rows 0..12, W_h2h2 rows 0..nr-1
    {
        const float4* s1 = (const float4*)(W_h2h1 + (size_t)r0 * H_DIM);
        const float4* s2 = (const float4*)(W_h2h2 + (size_t)r0 * H_DIM);
        float4* d1 = (float4*)Wsh1;
        float4* d2 = (float4*)Wsh2;
        const int n4a = W1ROWS * (H_DIM / 4);          // 13 rows (nr >= 13)
        const int n4b = nr * (H_DIM / 4);
        for (int i = tid; i < n4a; i += NTHR) d1[i] = s1[i];
        for (int i = tid; i < n4b; i += NTHR) d2[i] = s2[i];
    }

    // Register-stationary W_i2h2 slices (cols 4*tid.. and 1024+4*tid..)
    float4 wr0[MAXR], wr1[MAXR];
#pragma unroll
    for (int rr = 0; rr < MAXR; rr++) {
        int r = (rr < nr) ? (r0 + rr) : r0;
        const float4* wp = (const float4*)(W_i2h2 + (size_t)r * H_DIM);
        wr0[rr] = wp[tid];
        wr1[rr] = wp[tid + 256];
    }
    // Register-stationary W_h2h1 row 13 slice (clamped for nr==13; discarded)
    float4 wrA0, wrA1;
    {
        int r = r0 + ((13 < nr) ? 13 : (nr - 1));
        const float4* wp = (const float4*)(W_h2h1 + (size_t)r * H_DIM);
        wrA0 = wp[tid];
        wrA1 = wp[tid + 256];
    }

    unsigned tgt = GRID_P;
    grid_bar(tgt);                         // h1(0), h2(-1), caches visible

    const int frow = tid >> 3;             // stage-2 row (0..27 for tid<224)
    const int fs = tid & 7;                // stage-2 float4 index (0..7)
    // clamped prefetch row for the A-part (rows 14..27 -> pre1 row)
    const int prowA = (frow >= MAXR && frow < 2 * MAXR)
                      ? (((frow - MAXR) < nr) ? (frow - MAXR) : (nr - 1)) : 0;

    for (int t = 0; t < T_SEQ - 1; t++) {
        const int q = t & 1;

        // prefetch pre1[t+1] for the A stage-2 rows
        float pre = __ldg(&g_pre1[(size_t)(t + 1) * H_DIM + r0 + prowA]);

        // single post-barrier load: h1(t) and h2(t-1) slices
        float4 n0 = __ldcg((const float4*)g_h1[q] + tid);
        float4 n1 = __ldcg((const float4*)g_h1[q] + tid + 256);
        float4 c0 = __ldcg((const float4*)g_h2[1 - q] + tid);
        float4 c1 = __ldcg((const float4*)g_h2[1 - q] + tid + 256);

        // ---- fused stage-1 (3 shuffles, 4 partials/warp) ----
#pragma unroll
        for (int rr = 0; rr < W1ROWS; rr++) {
            const float* w1 = Wsh1 + rr * H_DIM;
            const float* w2 = Wsh2 + rr * H_DIM;
            float4 w10 = *(const float4*)(w1 + 4 * tid);
            float4 w11 = *(const float4*)(w1 + 4 * tid + 1024);
            float4 w20 = *(const float4*)(w2 + 4 * tid);
            float4 w21 = *(const float4*)(w2 + 4 * tid + 1024);
            float accA = dot4(w10, n0) + dot4(w11, n1);
            float accB = dot4(wr0[rr], n0) + dot4(wr1[rr], n1)
                       + dot4(w20, c0) + dot4(w21, c1);
            accA += __shfl_xor_sync(0xffffffffu, accA, 16);
            accB += __shfl_xor_sync(0xffffffffu, accB, 16);
            accA += __shfl_xor_sync(0xffffffffu, accA, 8);
            accB += __shfl_xor_sync(0xffffffffu, accB, 8);
            accA += __shfl_xor_sync(0xffffffffu, accA, 4);
            accB += __shfl_xor_sync(0xffffffffu, accB, 4);
            if (lane < 4) {
                red[rr][wid * 4 + lane] = accB;
                red[MAXR + rr][wid * 4 + lane] = accA;
            }
        }
        {   // rr = 13: A-row from registers, B-row from SMEM row 13 of Wsh2
            const float* w2 = Wsh2 + 13 * H_DIM;
            float4 w20 = *(const float4*)(w2 + 4 * tid);
            float4 w21 = *(const float4*)(w2 + 4 * tid + 1024);
            float accA = dot4(wrA0, n0) + dot4(wrA1, n1);
            float accB = dot4(wr0[13], n0) + dot4(wr1[13], n1)
                       + dot4(w20, c0) + dot4(w21, c1);
            accA += __shfl_xor_sync(0xffffffffu, accA, 16);
            accB += __shfl_xor_sync(0xffffffffu, accB, 16);
            accA += __shfl_xor_sync(0xffffffffu, accA, 8);
            accB += __shfl_xor_sync(0xffffffffu, accB, 8);
            accA += __shfl_xor_sync(0xffffffffu, accA, 4);
            accB += __shfl_xor_sync(0xffffffffu, accB, 4);
            if (lane < 4) {
                red[13][wid * 4 + lane] = accB;
                red[MAXR + 13][wid * 4 + lane] = accA;
            }
        }
        __syncthreads();

        // ---- stage-2: 28 rows x 8 threads (7 FULL warps) ----
        if (tid < 224) {
            float4 v = *((const float4*)red[frow] + fs);
            float x = (v.x + v.y) + (v.z + v.w);
            x += __shfl_down_sync(0xffffffffu, x, 4, 8);
            x += __shfl_down_sync(0xffffffffu, x, 2, 8);
            x += __shfl_down_sync(0xffffffffu, x, 1, 8);
            if (fs == 0) {
                if (frow < MAXR) {                       // B: h2(t)
                    if (frow < nr)
                        g_h2[q][r0 + frow] = tanhf(bsum[frow] + x);
                } else {                                 // A: h1(t+1)
                    int ar = frow - MAXR;
                    if (ar < nr)
                        g_h1[1 - q][r0 + ar] = tanhf(pre + x);
                }
            }
        }
        tgt += GRID_P;
        grid_bar(tgt);     // the ONLY grid barrier of the step
    }

    // ---- epilogue t = 511: h2(511) only ----
    {
        float4 n0 = __ldcg((const float4*)g_h1[1] + tid);
        float4 n1 = __ldcg((const float4*)g_h1[1] + tid + 256);
        float4 c0 = __ldcg((const float4*)g_h2[0] + tid);
        float4 c1 = __ldcg((const float4*)g_h2[0] + tid + 256);
#pragma unroll
        for (int rr = 0; rr < MAXR; rr++) {
            const float* w2 = Wsh2 + rr * H_DIM;
            float4 w20 = *(const float4*)(w2 + 4 * tid);
            float4 w21 = *(const float4*)(w2 + 4 * tid + 1024);
            float accB = dot4(wr0[rr], n0) + dot4(wr1[rr], n1)
                       + dot4(w20, c0) + dot4(w21, c1);
            accB += __shfl_xor_sync(0xffffffffu, accB, 16);
            accB += __shfl_xor_sync(0xffffffffu, accB, 8);
            accB += __shfl_xor_sync(0xffffffffu, accB, 4);
            if (lane < 4) red[rr][wid * 4 + lane] = accB;
        }
        __syncthreads();
        if (tid < 224) {                    // 7 FULL warps; rows >=14 discarded
            float4 v = *((const float4*)red[frow] + fs);
            float x = (v.x + v.y) + (v.z + v.w);
            x += __shfl_down_sync(0xffffffffu, x, 4, 8);
            x += __shfl_down_sync(0xffffffffu, x, 2, 8);
            x += __shfl_down_sync(0xffffffffu, x, 1, 8);
            if (fs == 0 && frow < nr)
                g_h2[1][r0 + frow] = tanhf(bsum[frow] + x);
        }
    }
    // final h2 (t=511) is in g_h2[1]; kernel boundary publishes it
}

// ---------------------------------------------------------------------------
// Kernel 3: out = h2_final @ W_h2o2^T + b_h2o2
// ---------------------------------------------------------------------------
__global__ __launch_bounds__(256) void out_gemv(
    const float* __restrict__ W, const float* __restrict__ b,
    float* __restrict__ out)
{
    const int lane = threadIdx.x & 31;
    const int warp = threadIdx.x >> 5;
    const int row = blockIdx.x * 8 + warp;
    const float4* wp = (const float4*)(W + (size_t)row * H_DIM);
    const float4* hp = (const float4*)g_h2[1];
    float acc = 0.f;
#pragma unroll
    for (int i = 0; i < 16; i++) {
        float4 w4 = __ldg(wp + i * 32 + lane);
        float4 h4 = __ldcg(hp + i * 32 + lane);
        acc += dot4(w4, h4);
    }
#pragma unroll
    for (int off = 16; off; off >>= 1)
        acc += __shfl_xor_sync(0xffffffffu, acc, off);
    if (lane == 0) out[row] = acc + __ldg(b + row);
}

// ---------------------------------------------------------------------------
extern "C" void kernel_launch(void* const* d_in, const int* in_sizes, int n_in,
                              void* d_out, int out_size)
{
    const float* word   = (const float*)d_in[0];
    const float* W_i2h1 = (const float*)d_in[1];
    const float* b_i2h1 = (const float*)d_in[2];
    const float* W_h2h1 = (const float*)d_in[3];
    const float* b_h2h1 = (const float*)d_in[4];
    // d_in[5], d_in[6]: W_h2o1 / b_h2o1 — dead code in reference
    const float* W_i2h2 = (const float*)d_in[7];
    const float* b_i2h2 = (const float*)d_in[8];
    const float* W_h2h2 = (const float*)d_in[9];
    const float* b_h2h2 = (const float*)d_in[10];
    const float* W_h2o2 = (const float*)d_in[11];
    const float* b_h2o2 = (const float*)d_in[12];
    float* out = (float*)d_out;

    cudaFuncSetAttribute(rnn_persistent,
                         cudaFuncAttributeMaxDynamicSharedMemorySize, SMEM_BYTES);

    dim3 pg(H_DIM / BJ, T_SEQ / BT);                 // 16 x 8 = 128 blocks
    pre_gemm<<<pg, 128>>>(word, W_i2h1, b_i2h1, b_h2h1);
    rnn_persistent<<<GRID_P, NTHR, SMEM_BYTES>>>(W_h2h1, W_i2h2, b_i2h2,
                                                 W_h2h2, b_h2h2);
    out_gemv<<<OUT_DIM / 8, 256>>>(W_h2o2, b_h2o2, out);
}

// round 17
// speedup vs baseline: 1.4994x; 1.0624x over previous
#include <cuda_runtime.h>
#include <math.h>

#define T_SEQ   512
#define IN_DIM  1024
#define H_DIM   2048
#define OUT_DIM 1024
#define GRID_P  148
#define NTHR    256
#define MAXR    14                          // ceil(2048/148)
#define W1ROWS  13                          // Wsh1 rows in SMEM (row 13 -> regs)
#define SMEM_BYTES ((W1ROWS + MAXR) * H_DIM * 4)   // 221184 B dynamic

// ---------------- device scratch (no allocation allowed) --------------------
__device__ float g_pre1[(size_t)T_SEQ * H_DIM];   // x@W_i2h1^T + b_i2h1 + b_h2h1
__device__ float g_h1[2][H_DIM];
__device__ float g_h2[2][H_DIM];
__device__ unsigned g_bar_ctr;                    // monotonic arrival counter

__device__ __forceinline__ float dot4(float4 a, float4 b) {
    return a.x * b.x + a.y * b.y + a.z * b.z + a.w * b.w;
}

// Grid barrier, return-free arrive: red.release.gpu.add (REDG -- no
// return-path serialization) + acquire spin by thread 0 on the single
// counter line. Monotonic: barrier k waits for ctr >= k*GRID_P.
// Reset by pre_gemm each replay.
__device__ __forceinline__ void grid_bar(unsigned target) {
    __syncthreads();
    if (threadIdx.x == 0) {
        asm volatile("red.release.gpu.add.u32 [%0], %1;"
                     :: "l"(&g_bar_ctr), "r"(1u) : "memory");
        unsigned v;
        do {
            asm volatile("ld.acquire.gpu.u32 %0, [%1];"
                         : "=r"(v) : "l"(&g_bar_ctr) : "memory");
        } while (v < target);
    }
    __syncthreads();
}

// ---------------------------------------------------------------------------
// Kernel 1: pre1[t][j] = x[t] @ W_i2h1[j] + b_i2h1[j] + b_h2h1[j]
// (128 CTAs of 128 threads, 64x128 tile, 8x8 microtile, ~94.7us)
// ---------------------------------------------------------------------------
#define BT 64
#define BJ 128
#define BK 32

__global__ __launch_bounds__(128) void pre_gemm(
    const float* __restrict__ X, const float* __restrict__ W,
    const float* __restrict__ b1, const float* __restrict__ b2)
{
    // reset barrier counter for the persistent kernel (each replay)
    if (blockIdx.x == 0 && blockIdx.y == 0 && threadIdx.x == 0)
        g_bar_ctr = 0;

    __shared__ float Xs[BT][BK + 1];
    __shared__ float Ws[BJ][BK + 1];
    const int tid = threadIdx.x;
    const int bt = blockIdx.y * BT;
    const int bj = blockIdx.x * BJ;
    const int tx = tid & 15;
    const int ty = tid >> 4;

    float acc[8][8];
#pragma unroll
    for (int i = 0; i < 8; i++)
#pragma unroll
        for (int j = 0; j < 8; j++) acc[i][j] = 0.f;

    for (int k0 = 0; k0 < IN_DIM; k0 += BK) {
#pragma unroll
        for (int i = tid; i < BT * (BK / 4); i += 128) {
            int t = i / (BK / 4), kq = i % (BK / 4);
            float4 v = *(const float4*)(X + (size_t)(bt + t) * IN_DIM + k0 + kq * 4);
            Xs[t][kq * 4 + 0] = v.x; Xs[t][kq * 4 + 1] = v.y;
            Xs[t][kq * 4 + 2] = v.z; Xs[t][kq * 4 + 3] = v.w;
        }
#pragma unroll
        for (int i = tid; i < BJ * (BK / 4); i += 128) {
            int j = i / (BK / 4), kq = i % (BK / 4);
            float4 v = *(const float4*)(W + (size_t)(bj + j) * IN_DIM + k0 + kq * 4);
            Ws[j][kq * 4 + 0] = v.x; Ws[j][kq * 4 + 1] = v.y;
            Ws[j][kq * 4 + 2] = v.z; Ws[j][kq * 4 + 3] = v.w;
        }
        __syncthreads();
#pragma unroll 8
        for (int kk = 0; kk < BK; kk++) {
            float a[8], b[8];
#pragma unroll
            for (int i = 0; i < 8; i++) a[i] = Xs[ty * 8 + i][kk];
#pragma unroll
            for (int j = 0; j < 8; j++) b[j] = Ws[tx * 8 + j][kk];
#pragma unroll
            for (int i = 0; i < 8; i++)
#pragma unroll
                for (int j = 0; j < 8; j++) acc[i][j] += a[i] * b[j];
        }
        __syncthreads();
    }
#pragma unroll
    for (int i = 0; i < 8; i++) {
        int t = bt + ty * 8 + i;
#pragma unroll
        for (int j = 0; j < 8; j++) {
            int col = bj + tx * 8 + j;
            g_pre1[(size_t)t * H_DIM + col] = acc[i][j] + __ldg(b1 + col) + __ldg(b2 + col);
        }
    }
}

// ---------------------------------------------------------------------------
// Kernel 2: persistent RNN. FUSED phases, ONE grid barrier per step.
// Wsh1 rows 0..12 in SMEM, W_h2h1 row 13 in registers.
// Stage-1: TWO xor-shuffles (depth 2) -> 8 partials/warp -> red[28][64].
// Stage-2: 28 rows x 8 threads (tid<224 = 7 FULL warps), 2x LDS.128 +
//          3 width-8 shfl_down (absorbs the third reduction level).
// ---------------------------------------------------------------------------
__global__ __launch_bounds__(NTHR, 1) void rnn_persistent(
    const float* __restrict__ W_h2h1,
    const float* __restrict__ W_i2h2,
    const float* __restrict__ b_i2h2,
    const float* __restrict__ W_h2h2,
    const float* __restrict__ b_h2h2)
{
    extern __shared__ float smem[];
    float* Wsh1 = smem;                         // [W1ROWS][2048]
    float* Wsh2 = smem + W1ROWS * H_DIM;        // [MAXR][2048]
    __shared__ __align__(16) float red[2 * MAXR][64];   // 7168B
    __shared__ float bsum[16];

    const int tid = threadIdx.x;
    const int bid = blockIdx.x;
    const int r0 = (bid * H_DIM) / GRID_P;
    const int r1 = ((bid + 1) * H_DIM) / GRID_P;
    const int nr = r1 - r0;                // 13 or 14
    const int lane = tid & 31;
    const int wid = tid >> 5;

    // h1(0) = tanh(pre1[0]) (h1(-1)=0); h2(-1) = 0 lives in g_h2[1]
    if (tid < nr) {
        g_h1[0][r0 + tid] = tanhf(__ldg(&g_pre1[r0 + tid]));
        g_h2[1][r0 + tid] = 0.f;
        bsum[tid] = __ldg(b_i2h2 + r0 + tid) + __ldg(b_h2h2 + r0 + tid);
    }

    // SMEM weight caches: W_h2h1 rows 0..12, W_h2h2 rows 0..nr-1
    {
        const float4* s1 = (const float4*)(W_h2h1 + (size_t)r0 * H_DIM);
        const float4* s2 = (const float4*)(W_h2h2 + (size_t)r0 * H_DIM);
        float4* d1 = (float4*)Wsh1;
        float4* d2 = (float4*)Wsh2;
        const int n4a = W1ROWS * (H_DIM / 4);          // 13 rows (nr >= 13)
        const int n4b = nr * (H_DIM / 4);
        for (int i = tid; i < n4a; i += NTHR) d1[i] = s1[i];
        for (int i = tid; i < n4b; i += NTHR) d2[i] = s2[i];
    }

    // Register-stationary W_i2h2 slices (cols 4*tid.. and 1024+4*tid..)
    float4 wr0[MAXR], wr1[MAXR];
#pragma unroll
    for (int rr = 0; rr < MAXR; rr++) {
        int r = (rr < nr) ? (r0 + rr) : r0;
        const float4* wp = (const float4*)(W_i2h2 + (size_t)r * H_DIM);
        wr0[rr] = wp[tid];
        wr1[rr] = wp[tid + 256];
    }
    // Register-stationary W_h2h1 row 13 slice (clamped for nr==13; discarded)
    float4 wrA0, wrA1;
    {
        int r = r0 + ((13 < nr) ? 13 : (nr - 1));
        const float4* wp = (const float4*)(W_h2h1 + (size_t)r * H_DIM);
        wrA0 = wp[tid];
        wrA1 = wp[tid + 256];
    }

    unsigned tgt = GRID_P;
    grid_bar(tgt);                         // h1(0), h2(-1), caches visible

    const int frow = tid >> 3;             // stage-2 row (0..27 for tid<224)
    const int fs = tid & 7;                // stage-2 sub-index (0..7)
    // clamped prefetch row for the A-part (rows 14..27 -> pre1 row)
    const int prowA = (frow >= MAXR && frow < 2 * MAXR)
                      ? (((frow - MAXR) < nr) ? (frow - MAXR) : (nr - 1)) : 0;

    for (int t = 0; t < T_SEQ - 1; t++) {
        const int q = t & 1;

        // prefetch pre1[t+1] for the A stage-2 rows
        float pre = __ldg(&g_pre1[(size_t)(t + 1) * H_DIM + r0 + prowA]);

        // single post-barrier load: h1(t) and h2(t-1) slices
        float4 n0 = __ldcg((const float4*)g_h1[q] + tid);
        float4 n1 = __ldcg((const float4*)g_h1[q] + tid + 256);
        float4 c0 = __ldcg((const float4*)g_h2[1 - q] + tid);
        float4 c1 = __ldcg((const float4*)g_h2[1 - q] + tid + 256);

        // ---- fused stage-1 (2 shuffles, 8 partials/warp) ----
#pragma unroll
        for (int rr = 0; rr < W1ROWS; rr++) {
            const float* w1 = Wsh1 + rr * H_DIM;
            const float* w2 = Wsh2 + rr * H_DIM;
            float4 w10 = *(const float4*)(w1 + 4 * tid);
            float4 w11 = *(const float4*)(w1 + 4 * tid + 1024);
            float4 w20 = *(const float4*)(w2 + 4 * tid);
            float4 w21 = *(const float4*)(w2 + 4 * tid + 1024);
            float accA = dot4(w10, n0) + dot4(w11, n1);
            float accB = dot4(wr0[rr], n0) + dot4(wr1[rr], n1)
                       + dot4(w20, c0) + dot4(w21, c1);
            accA += __shfl_xor_sync(0xffffffffu, accA, 16);
            accB += __shfl_xor_sync(0xffffffffu, accB, 16);
            accA += __shfl_xor_sync(0xffffffffu, accA, 8);
            accB += __shfl_xor_sync(0xffffffffu, accB, 8);
            if (lane < 8) {
                red[rr][wid * 8 + lane] = accB;
                red[MAXR + rr][wid * 8 + lane] = accA;
            }
        }
        {   // rr = 13: A-row from registers, B-row from SMEM row 13 of Wsh2
            const float* w2 = Wsh2 + 13 * H_DIM;
            float4 w20 = *(const float4*)(w2 + 4 * tid);
            float4 w21 = *(const float4*)(w2 + 4 * tid + 1024);
            float accA = dot4(wrA0, n0) + dot4(wrA1, n1);
            float accB = dot4(wr0[13], n0) + dot4(wr1[13], n1)
                       + dot4(w20, c0) + dot4(w21, c1);
            accA += __shfl_xor_sync(0xffffffffu, accA, 16);
            accB += __shfl_xor_sync(0xffffffffu, accB, 16);
            accA += __shfl_xor_sync(0xffffffffu, accA, 8);
            accB += __shfl_xor_sync(0xffffffffu, accB, 8);
            if (lane < 8) {
                red[13][wid * 8 + lane] = accB;
                red[MAXR + 13][wid * 8 + lane] = accA;
            }
        }
        __syncthreads();

        // ---- stage-2: 28 rows x 8 threads (7 FULL warps), 64 partials ----
        if (tid < 224) {
            float4 v0 = *((const float4*)red[frow] + fs * 2);
            float4 v1 = *((const float4*)red[frow] + fs * 2 + 1);
            float x = ((v0.x + v0.y) + (v0.z + v0.w))
                    + ((v1.x + v1.y) + (v1.z + v1.w));
            x += __shfl_down_sync(0xffffffffu, x, 4, 8);
            x += __shfl_down_sync(0xffffffffu, x, 2, 8);
            x += __shfl_down_sync(0xffffffffu, x, 1, 8);
            if (fs == 0) {
                if (frow < MAXR) {                       // B: h2(t)
                    if (frow < nr)
                        g_h2[q][r0 + frow] = tanhf(bsum[frow] + x);
                } else {                                 // A: h1(t+1)
                    int ar = frow - MAXR;
                    if (ar < nr)
                        g_h1[1 - q][r0 + ar] = tanhf(pre + x);
                }
            }
        }
        tgt += GRID_P;
        grid_bar(tgt);     // the ONLY grid barrier of the step
    }

    // ---- epilogue t = 511: h2(511) only ----
    {
        float4 n0 = __ldcg((const float4*)g_h1[1] + tid);
        float4 n1 = __ldcg((const float4*)g_h1[1] + tid + 256);
        float4 c0 = __ldcg((const float4*)g_h2[0] + tid);
        float4 c1 = __ldcg((const float4*)g_h2[0] + tid + 256);
#pragma unroll
        for (int rr = 0; rr < MAXR; rr++) {
            const float* w2 = Wsh2 + rr * H_DIM;
            float4 w20 = *(const float4*)(w2 + 4 * tid);
            float4 w21 = *(const float4*)(w2 + 4 * tid + 1024);
            float accB = dot4(wr0[rr], n0) + dot4(wr1[rr], n1)
                       + dot4(w20, c0) + dot4(w21, c1);
            accB += __shfl_xor_sync(0xffffffffu, accB, 16);
            accB += __shfl_xor_sync(0xffffffffu, accB, 8);
            if (lane < 8) red[rr][wid * 8 + lane] = accB;
        }
        __syncthreads();
        if (tid < 224) {                    // 7 FULL warps; rows >=14 discarded
            float4 v0 = *((const float4*)red[frow] + fs * 2);
            float4 v1 = *((const float4*)red[frow] + fs * 2 + 1);
            float x = ((v0.x + v0.y) + (v0.z + v0.w))
                    + ((v1.x + v1.y) + (v1.z + v1.w));
            x += __shfl_down_sync(0xffffffffu, x, 4, 8);
            x += __shfl_down_sync(0xffffffffu, x, 2, 8);
            x += __shfl_down_sync(0xffffffffu, x, 1, 8);
            if (fs == 0 && frow < nr)
                g_h2[1][r0 + frow] = tanhf(bsum[frow] + x);
        }
    }
    // final h2 (t=511) is in g_h2[1]; kernel boundary publishes it
}

// ---------------------------------------------------------------------------
// Kernel 3: out = h2_final @ W_h2o2^T + b_h2o2
// ---------------------------------------------------------------------------
__global__ __launch_bounds__(256) void out_gemv(
    const float* __restrict__ W, const float* __restrict__ b,
    float* __restrict__ out)
{
    const int lane = threadIdx.x & 31;
    const int warp = threadIdx.x >> 5;
    const int row = blockIdx.x * 8 + warp;
    const float4* wp = (const float4*)(W + (size_t)row * H_DIM);
    const float4* hp = (const float4*)g_h2[1];
    float acc = 0.f;
#pragma unroll
    for (int i = 0; i < 16; i++) {
        float4 w4 = __ldg(wp + i * 32 + lane);
        float4 h4 = __ldcg(hp + i * 32 + lane);
        acc += dot4(w4, h4);
    }
#pragma unroll
    for (int off = 16; off; off >>= 1)
        acc += __shfl_xor_sync(0xffffffffu, acc, off);
    if (lane == 0) out[row] = acc + __ldg(b + row);
}

// ---------------------------------------------------------------------------
extern "C" void kernel_launch(void* const* d_in, const int* in_sizes, int n_in,
                              void* d_out, int out_size)
{
    const float* word   = (const float*)d_in[0];
    const float* W_i2h1 = (const float*)d_in[1];
    const float* b_i2h1 = (const float*)d_in[2];
    const float* W_h2h1 = (const float*)d_in[3];
    const float* b_h2h1 = (const float*)d_in[4];
    // d_in[5], d_in[6]: W_h2o1 / b_h2o1 — dead code in reference
    const float* W_i2h2 = (const float*)d_in[7];
    const float* b_i2h2 = (const float*)d_in[8];
    const float* W_h2h2 = (const float*)d_in[9];
    const float* b_h2h2 = (const float*)d_in[10];
    const float* W_h2o2 = (const float*)d_in[11];
    const float* b_h2o2 = (const float*)d_in[12];
    float* out = (float*)d_out;

    cudaFuncSetAttribute(rnn_persistent,
                         cudaFuncAttributeMaxDynamicSharedMemorySize, SMEM_BYTES);

    dim3 pg(H_DIM / BJ, T_SEQ / BT);                 // 16 x 8 = 128 blocks
    pre_gemm<<<pg, 128>>>(word, W_i2h1, b_i2h1, b_h2h1);
    rnn_persistent<<<GRID_P, NTHR, SMEM_BYTES>>>(W_h2h1, W_i2h2, b_i2h2,
                                                 W_h2h2, b_h2h2);
    out_gemv<<<OUT_DIM / 8, 256>>>(W_h2o2, b_h2o2, out);
}